// round 8
// baseline (speedup 1.0000x reference)
#include <cuda_runtime.h>
#include <cstdint>

#define NB 4
#define NN 4096
#define ND 16
#define KK 10
#define TT 12
#define RPW 4           // rows per warp
#define RPB 32          // rows per block (8 warps * RPW)
#define TILE_M 256      // m-tile held in shared
#define ITS (TILE_M / 32)
#define FULLM 0xFFFFFFFFu

typedef unsigned long long u64;

// state embeddings: [B][N][D]
__device__ float g_emb[NB * NN * ND];

// ---------------------------------------------------------------------------
// f32x2 packed helpers (Blackwell FFMA2 path, PTX-only)
// ---------------------------------------------------------------------------
__device__ __forceinline__ u64 mul2(u64 a, u64 b) {
    u64 d; asm("mul.rn.f32x2 %0, %1, %2;" : "=l"(d) : "l"(a), "l"(b)); return d;
}
__device__ __forceinline__ u64 fma2(u64 a, u64 b, u64 c) {
    u64 d; asm("fma.rn.f32x2 %0, %1, %2, %3;" : "=l"(d) : "l"(a), "l"(b), "l"(c)); return d;
}
__device__ __forceinline__ float red2(u64 a) {
    unsigned lo, hi;
    asm("mov.b64 {%0, %1}, %2;" : "=r"(lo), "=r"(hi) : "l"(a));
    return __uint_as_float(lo) + __uint_as_float(hi);
}
__device__ __forceinline__ float val_of(u64 e) {
    return __uint_as_float((unsigned)(e >> 32));
}

// ---------------------------------------------------------------------------
// Kernel 1: state_emb[b,n,j] = tanh(x[b,T-1,n,0] * W[j] + bfc[j])
// ---------------------------------------------------------------------------
__global__ void emb_kernel(const float* __restrict__ x,
                           const float* __restrict__ W,
                           const float* __restrict__ bfc) {
    int i = blockIdx.x * blockDim.x + threadIdx.x;   // 0 .. B*N-1
    if (i >= NB * NN) return;
    int b = i >> 12;
    int n = i & (NN - 1);
    float xv = x[((size_t)b * TT + (TT - 1)) * NN + n];
    float4* dst = reinterpret_cast<float4*>(&g_emb[(size_t)i * ND]);
#pragma unroll
    for (int j4 = 0; j4 < 4; j4++) {
        float4 o;
        o.x = tanhf(fmaf(xv, W[j4 * 4 + 0], bfc[j4 * 4 + 0]));
        o.y = tanhf(fmaf(xv, W[j4 * 4 + 1], bfc[j4 * 4 + 1]));
        o.z = tanhf(fmaf(xv, W[j4 * 4 + 2], bfc[j4 * 4 + 2]));
        o.w = tanhf(fmaf(xv, W[j4 * 4 + 3], bfc[j4 * 4 + 3]));
        dst[j4] = o;
    }
}

// ---------------------------------------------------------------------------
// Warp-collective insert of candidates (ballot mask msk, per-lane score s)
// into the distributed sorted top-10 (lane k holds k-th largest, k<10).
// Candidate index = mbase + src_lane. Stale candidates (pos==10) are no-ops.
// ---------------------------------------------------------------------------
__device__ __forceinline__ void warp_insert(u64& ent, unsigned msk, float s,
                                            unsigned mbase, int lane) {
    while (msk) {
        int src = __ffs(msk) - 1;
        msk &= msk - 1;
        float pv = __shfl_sync(FULLM, s, src);
        u64 p = ((u64)__float_as_uint(pv) << 32) | (u64)(mbase + src);
        unsigned gmask = __ballot_sync(FULLM, ent > p) & 0x3FFu;
        int pos = __popc(gmask);
        u64 shifted = __shfl_up_sync(FULLM, ent, 1);
        if (lane >= pos && lane < KK) ent = (lane == pos) ? p : shifted;
    }
}

// ---------------------------------------------------------------------------
// Kernel 2: fused A_dyn rows + exact warp-wide top-10 + softmax + output.
// Grid: (NN/RPB, NB), 256 threads, 4 blocks/SM (regs <= 64, no e[] in regs:
// row embeddings live in shared, re-read per iteration via LDS broadcast).
// ---------------------------------------------------------------------------
__global__ __launch_bounds__(256, 4) void fused_kernel(
    const float* __restrict__ Aphys,
    const float* __restrict__ alpha_p,
    float* __restrict__ out) {
    __shared__ __align__(16) float4 tile4[TILE_M * 5];  // stride-5 f4
    __shared__ u64 shtop[RPB][KK];
    __shared__ __align__(16) float sh_emb[RPB * ND];
    __shared__ float sh_base[RPB], sh_c1[RPB], sh_vmax[RPB];

    const int t = threadIdx.x;
    const int lane = t & 31;
    const int g = t >> 5;
    const int b = blockIdx.y;
    const int n0 = blockIdx.x * RPB;

    // stage this block's row embeddings (512 floats)
    sh_emb[t] = g_emb[((size_t)b * NN + n0 + (t >> 4)) * ND + (t & 15)];
    sh_emb[t + 256] =
        g_emb[((size_t)b * NN + n0 + ((t + 256) >> 4)) * ND + (t & 15)];
    __syncthreads();

    const int r0 = RPW * g;

    u64 ent[RPW];
    float thr[RPW];
#pragma unroll
    for (int r = 0; r < RPW; r++) { ent[r] = 0ULL; thr[r] = 0.f; }

    const float* embf = g_emb + (size_t)b * NN * ND;

    for (int tile = 0; tile < NN / TILE_M; tile++) {
        __syncthreads();
        {   // cooperative stage: thread t loads emb row (tile*256 + t)
            const float4* src = reinterpret_cast<const float4*>(
                embf + (size_t)(tile * TILE_M + t) * ND);
            float4 v0 = src[0], v1 = src[1], v2 = src[2], v3 = src[3];
            tile4[t * 5 + 0] = v0;
            tile4[t * 5 + 1] = v1;
            tile4[t * 5 + 2] = v2;
            tile4[t * 5 + 3] = v3;
        }
        __syncthreads();

#pragma unroll
        for (int it = 0; it < ITS; it++) {
            const int ml = it * 32 + lane;
            const ulonglong2* q =
                reinterpret_cast<const ulonglong2*>(tile4 + ml * 5);
            ulonglong2 q0 = q[0], q1 = q[1], q2 = q[2], q3 = q[3];

            float s[RPW];
#pragma unroll
            for (int r = 0; r < RPW; r++) {
                // row embedding via LDS broadcast (warp-uniform address):
                // transient regs, short live range -> fits 64-reg budget
                const ulonglong2* ep = reinterpret_cast<const ulonglong2*>(
                    &sh_emb[(r0 + r) * ND]);
                ulonglong2 E0 = ep[0], E1 = ep[1], E2 = ep[2], E3 = ep[3];
                u64 acc = mul2(E0.x, q0.x);
                acc = fma2(E0.y, q0.y, acc);
                acc = fma2(E1.x, q1.x, acc);
                acc = fma2(E1.y, q1.y, acc);
                acc = fma2(E2.x, q2.x, acc);
                acc = fma2(E2.y, q2.y, acc);
                acc = fma2(E3.x, q3.x, acc);
                acc = fma2(E3.y, q3.y, acc);
                s[r] = red2(acc);
            }

            const unsigned mbase = (unsigned)(tile * TILE_M + it * 32);
#pragma unroll
            for (int r = 0; r < RPW; r++) {
                unsigned msk = __ballot_sync(FULLM, s[r] > thr[r]);
                if (msk) {
                    warp_insert(ent[r], msk, s[r], mbase, lane);
                    thr[r] = __uint_as_float(
                        (unsigned)(__shfl_sync(FULLM, ent[r], KK - 1) >> 32));
                }
            }
        }
    }

    // publish warp-wide sorted top-10 (already distributed; no merge needed)
    if (lane < KK) {
#pragma unroll
        for (int r = 0; r < RPW; r++) shtop[r0 + r][lane] = ent[r];
    }
    __syncwarp();

    const float alpha = *alpha_p;
    const float a = 1.f / (1.f + expf(-alpha));
    const float oma = 1.f - a;

    // per-row softmax constants (lane 0 of each warp handles its 4 rows)
    if (lane == 0) {
#pragma unroll
        for (int rr = 0; rr < RPW; rr++) {
            int r = r0 + rr;
            float vmax = val_of(shtop[r][0]);   // >= 0
            float s = 0.f;
#pragma unroll
            for (int k = 0; k < KK; k++) s += expf(val_of(shtop[r][k]) - vmax);
            float S = s + (float)(NN - KK) * expf(-vmax);
            float c1 = oma / S;
            sh_c1[r] = c1;
            sh_vmax[r] = vmax;
            sh_base[r] = c1 * expf(-vmax);
        }
    }
    __syncthreads();

    // Phase 3: out = a*A_phys + base for all m (coalesced float4, streaming st)
    const float4* ap_base = reinterpret_cast<const float4*>(Aphys);
    float4* out4 = reinterpret_cast<float4*>(out) + (size_t)b * NN * (NN / 4);
    for (int r = 0; r < RPB; r++) {
        int row = n0 + r;
        float base = sh_base[r];
        const float4* ap = ap_base + (size_t)row * (NN / 4);
        float4* op = out4 + (size_t)row * (NN / 4);
#pragma unroll
        for (int u = 0; u < (NN / 4) / 256; u++) {
            int i = u * 256 + t;
            float4 v = ap[i];
            float4 o;
            o.x = fmaf(a, v.x, base);
            o.y = fmaf(a, v.y, base);
            o.z = fmaf(a, v.z, base);
            o.w = fmaf(a, v.w, base);
            __stcs(&op[i], o);
        }
    }
    __syncthreads();

    // Phase 4: scatter fix-ups for top-K entries (skip zero placeholders)
    for (int i = t; i < RPB * KK; i += 256) {
        int r = i / KK, k = i - r * KK;
        u64 ee = shtop[r][k];
        if (ee != 0ULL) {
            unsigned idx = (unsigned)ee;
            float v = val_of(ee);
            int row = n0 + r;
            float pv = Aphys[(size_t)row * NN + idx];
            out[((size_t)b * NN + row) * NN + idx] =
                fmaf(a, pv, sh_c1[r] * expf(v - sh_vmax[r]));
        }
    }
}

// ---------------------------------------------------------------------------
extern "C" void kernel_launch(void* const* d_in, const int* in_sizes, int n_in,
                              void* d_out, int out_size) {
    const float* x     = (const float*)d_in[0];
    const float* Aphys = (const float*)d_in[1];
    const float* Wfc   = (const float*)d_in[2];
    const float* bfc   = (const float*)d_in[3];
    const float* alpha = (const float*)d_in[4];
    float* out = (float*)d_out;

    emb_kernel<<<(NB * NN + 255) / 256, 256>>>(x, Wfc, bfc);
    dim3 grid(NN / RPB, NB);
    fused_kernel<<<grid, 256>>>(Aphys, alpha, out);
}